// round 1
// baseline (speedup 1.0000x reference)
#include <cuda_runtime.h>
#include <cuda_bf16.h>
#include <math.h>

// Problem constants
#define BATCH 4
#define DIM   256
#define C3    192
#define C1    64
#define HEADS 8
#define HD    32
#define HW    16384   // 128*128
#define IMG   128

// ---------------------------------------------------------------------------
// Device scratch (static; no allocations allowed)
// ---------------------------------------------------------------------------
__device__ float g_wq [BATCH * DIM * C3];        // per-batch effective q weights [b][256][192]
__device__ float g_wkv[BATCH * 2*DIM * C1];      // per-batch effective kv weights [b][512][64]
__device__ float g_tq [BATCH * DIM * HW];        // q pre-dwconv
__device__ float g_tkv[BATCH * 2*DIM * HW];      // kv pre-dwconv
__device__ float g_q  [BATCH * DIM * HW];        // q post-dwconv
__device__ float g_kv [BATCH * 2*DIM * HW];      // kv post-dwconv (k=first 256 ch, v=second)
__device__ float g_nq [BATCH * DIM];             // sum of squares of q rows
__device__ float g_nk [BATCH * DIM];             // sum of squares of k rows
__device__ float g_G  [BATCH * HEADS * HD * HD]; // raw Gram matrices
__device__ float g_Wc [BATCH * DIM * DIM];       // combined w_proj @ blockdiag(attn)

// ---------------------------------------------------------------------------
// Zero the atomically-accumulated buffers (must run every launch)
// ---------------------------------------------------------------------------
__global__ void zero_kernel() {
    int i = blockIdx.x * blockDim.x + threadIdx.x;
    if (i < BATCH * DIM) { g_nq[i] = 0.f; g_nk[i] = 0.f; }
    if (i < BATCH * HEADS * HD * HD) g_G[i] = 0.f;
}

// ---------------------------------------------------------------------------
// FiLM modulation folded into per-batch conv weights.
// scale[c] = 1 + (kv projection), then wq_eff = w_qR * scale_r, etc.
// ---------------------------------------------------------------------------
__global__ void modk_kernel(const float* __restrict__ k_v,
                            const float* __restrict__ w_kR,
                            const float* __restrict__ w_kI,
                            const float* __restrict__ w_qR,
                            const float* __restrict__ w_kvI) {
    int b = blockIdx.x;
    int t = threadIdx.x;
    __shared__ float sc[DIM];
    if (t < C3) {
        float s = 0.f;
        const float* kb = k_v + b * 256;
        for (int i = 0; i < 192; i++) s += kb[i] * w_kR[t * 192 + i];
        sc[t] = 1.f + s;
    } else {
        int o = t - C3;
        float s = 0.f;
        const float* kb = k_v + b * 256 + 192;
        for (int i = 0; i < 64; i++) s += kb[i] * w_kI[o * 64 + i];
        sc[t] = 1.f + s;
    }
    __syncthreads();
    for (int idx = t; idx < DIM * C3; idx += blockDim.x)
        g_wq[b * DIM * C3 + idx] = w_qR[idx] * sc[idx % C3];
    for (int idx = t; idx < 2 * DIM * C1; idx += blockDim.x)
        g_wkv[b * 2 * DIM * C1 + idx] = w_kvI[idx] * sc[C3 + (idx & 63)];
}

// ---------------------------------------------------------------------------
// Tiled fp32 GEMM: C[b][o][n] = sum_k W[b][o][k] * X[b][k + x_off_rows][n]
// Block tile 64(o) x 64(n), BK=16, 256 threads, 4x4 per thread.
// ---------------------------------------------------------------------------
__device__ __forceinline__ void gemm_body(const float* __restrict__ W,
                                          const float* __restrict__ X,
                                          float* __restrict__ C,
                                          int K, int OC,
                                          int x_bstride, int x_off) {
    int b  = blockIdx.z;
    int n0 = blockIdx.x * 64;
    int o0 = blockIdx.y * 64;
    const float* Wb = W + (size_t)b * OC * K + (size_t)o0 * K;
    const float* Xb = X + (size_t)b * x_bstride + x_off + n0;
    float*       Cb = C + (size_t)b * OC * HW + (size_t)o0 * HW + n0;

    __shared__ float Ws[16][68];  // [k][o], padded (272B rows, 16B aligned)
    __shared__ float Xs[16][64];  // [k][n]

    int tid = threadIdx.x;
    int tx = tid & 15;   // n group
    int ty = tid >> 4;   // o group

    float acc[4][4] = {};

    for (int k0 = 0; k0 < K; k0 += 16) {
        // W tile: 64 rows(o) x 16(k); thread: o=tid/4, k quad=(tid&3)*4
        {
            int o  = tid >> 2;
            int kq = (tid & 3) * 4;
            float4 wv = *reinterpret_cast<const float4*>(&Wb[(size_t)o * K + k0 + kq]);
            Ws[kq + 0][o] = wv.x; Ws[kq + 1][o] = wv.y;
            Ws[kq + 2][o] = wv.z; Ws[kq + 3][o] = wv.w;
        }
        // X tile: 16 rows(k) x 64(n); thread: k=tid/16, n quad=(tid&15)*4
        {
            int kk = tid >> 4;
            int nq = (tid & 15) * 4;
            float4 xv = *reinterpret_cast<const float4*>(&Xb[(size_t)(k0 + kk) * HW + nq]);
            *reinterpret_cast<float4*>(&Xs[kk][nq]) = xv;
        }
        __syncthreads();
        #pragma unroll
        for (int kk = 0; kk < 16; kk++) {
            float a[4], bb[4];
            *reinterpret_cast<float4*>(a)  = *reinterpret_cast<const float4*>(&Ws[kk][ty * 4]);
            *reinterpret_cast<float4*>(bb) = *reinterpret_cast<const float4*>(&Xs[kk][tx * 4]);
            #pragma unroll
            for (int i = 0; i < 4; i++)
                #pragma unroll
                for (int j = 0; j < 4; j++)
                    acc[i][j] += a[i] * bb[j];
        }
        __syncthreads();
    }
    #pragma unroll
    for (int i = 0; i < 4; i++) {
        float4 v = make_float4(acc[i][0], acc[i][1], acc[i][2], acc[i][3]);
        *reinterpret_cast<float4*>(&Cb[(size_t)(ty * 4 + i) * HW + tx * 4]) = v;
    }
}

__global__ void __launch_bounds__(256) gemm_q_kernel(const float* __restrict__ x) {
    gemm_body(g_wq, x, g_tq, C3, DIM, DIM * HW, 0);
}
__global__ void __launch_bounds__(256) gemm_kv_kernel(const float* __restrict__ x) {
    gemm_body(g_wkv, x, g_tkv, C1, 2 * DIM, DIM * HW, C3 * HW);
}
__global__ void __launch_bounds__(256) gemm_o_kernel(float* __restrict__ out) {
    gemm_body(g_Wc, g_kv, out, DIM, DIM, 2 * DIM * HW, DIM * HW);
}

// ---------------------------------------------------------------------------
// Depthwise 3x3 conv (SAME, zero pad, correlation) + row sum-of-squares
// accumulated for the first `normC` channels (feeds the L2 norm).
// grid: (8 chunks, C, B), 256 threads; each thread 8 pixels.
// ---------------------------------------------------------------------------
__device__ __forceinline__ void dwconv_body(const float* __restrict__ in,
                                            const float* __restrict__ w9,
                                            float* __restrict__ out,
                                            int C, float* norms, int normC) {
    int b = blockIdx.z, c = blockIdx.y, chunk = blockIdx.x;
    const float* ip = in + (size_t)(b * C + c) * HW;
    float*       op = out + (size_t)(b * C + c) * HW;
    float wv[9];
    #pragma unroll
    for (int i = 0; i < 9; i++) wv[i] = w9[c * 9 + i];
    float ss = 0.f;
    #pragma unroll
    for (int it = 0; it < 8; it++) {
        int p = chunk * 2048 + it * 256 + threadIdx.x;
        int y = p >> 7, x = p & 127;
        float s = 0.f;
        #pragma unroll
        for (int dy = -1; dy <= 1; dy++) {
            int yy = y + dy;
            if ((unsigned)yy < (unsigned)IMG) {
                const float* rp = ip + yy * IMG;
                #pragma unroll
                for (int dx = -1; dx <= 1; dx++) {
                    int xx = x + dx;
                    if ((unsigned)xx < (unsigned)IMG)
                        s += wv[(dy + 1) * 3 + dx + 1] * rp[xx];
                }
            }
        }
        op[p] = s;
        ss += s * s;
    }
    if (c < normC) {
        #pragma unroll
        for (int o = 16; o > 0; o >>= 1) ss += __shfl_down_sync(0xffffffffu, ss, o);
        __shared__ float red[8];
        if ((threadIdx.x & 31) == 0) red[threadIdx.x >> 5] = ss;
        __syncthreads();
        if (threadIdx.x < 8) {
            float v = red[threadIdx.x];
            #pragma unroll
            for (int o = 4; o > 0; o >>= 1) v += __shfl_down_sync(0x000000ffu, v, o, 8);
            if (threadIdx.x == 0) atomicAdd(&norms[b * DIM + c], v);
        }
    }
}

__global__ void __launch_bounds__(256) dwq_kernel(const float* __restrict__ w) {
    dwconv_body(g_tq, w, g_q, DIM, g_nq, DIM);
}
__global__ void __launch_bounds__(256) dwkv_kernel(const float* __restrict__ w) {
    dwconv_body(g_tkv, w, g_kv, 2 * DIM, g_nk, DIM);
}

// ---------------------------------------------------------------------------
// Gram matrices: G[b][h][c][d] = sum_n q[b][h*32+c][n] * k[b][h*32+d][n]
// grid: (32 n-chunks of 512, HEADS, BATCH); 256 threads.
// Thread handles (c = tid/8, d = tid%8 + {0,8,16,24}) -> conflict-free LDS.
// ---------------------------------------------------------------------------
__global__ void __launch_bounds__(256) gram_kernel() {
    int chunk = blockIdx.x, h = blockIdx.y, b = blockIdx.z;
    const float* qp = g_q  + (size_t)(b * DIM      + h * HD) * HW;
    const float* kp = g_kv + (size_t)(b * 2 * DIM  + h * HD) * HW;

    __shared__ float qs[32][68];
    __shared__ float ks[32][68];

    int t = threadIdx.x;
    int c  = t >> 3;
    int dq = t & 7;
    int row  = t >> 3;          // load row
    int lcol = (t & 7) * 8;     // load col base (8 floats per thread)

    float acc0 = 0.f, acc1 = 0.f, acc2 = 0.f, acc3 = 0.f;

    for (int s = 0; s < 8; s++) {
        int n0 = chunk * 512 + s * 64;
        float4 a0 = *reinterpret_cast<const float4*>(&qp[(size_t)row * HW + n0 + lcol]);
        float4 a1 = *reinterpret_cast<const float4*>(&qp[(size_t)row * HW + n0 + lcol + 4]);
        float4 b0 = *reinterpret_cast<const float4*>(&kp[(size_t)row * HW + n0 + lcol]);
        float4 b1 = *reinterpret_cast<const float4*>(&kp[(size_t)row * HW + n0 + lcol + 4]);
        __syncthreads();
        *reinterpret_cast<float4*>(&qs[row][lcol])     = a0;
        *reinterpret_cast<float4*>(&qs[row][lcol + 4]) = a1;
        *reinterpret_cast<float4*>(&ks[row][lcol])     = b0;
        *reinterpret_cast<float4*>(&ks[row][lcol + 4]) = b1;
        __syncthreads();
        #pragma unroll 8
        for (int j = 0; j < 64; j++) {
            float qv = qs[c][j];
            acc0 += qv * ks[dq     ][j];
            acc1 += qv * ks[dq +  8][j];
            acc2 += qv * ks[dq + 16][j];
            acc3 += qv * ks[dq + 24][j];
        }
    }
    float* Gp = &g_G[((size_t)(b * HEADS + h) * HD + c) * HD];
    atomicAdd(&Gp[dq],      acc0);
    atomicAdd(&Gp[dq + 8],  acc1);
    atomicAdd(&Gp[dq + 16], acc2);
    atomicAdd(&Gp[dq + 24], acc3);
}

// ---------------------------------------------------------------------------
// Finalize attention (normalize by L2 norms, temperature, softmax) and fold
// into w_proj: Wc[b][o][h*32+d] = sum_c w_proj[o][h*32+c] * attn[b][h][c][d]
// grid: (HEADS, BATCH), 256 threads.
// ---------------------------------------------------------------------------
__global__ void __launch_bounds__(256) attn_wc_kernel(const float* __restrict__ temp,
                                                      const float* __restrict__ w_proj) {
    int h = blockIdx.x, b = blockIdx.y;
    int t = threadIdx.x;
    __shared__ float As[HD][HD + 1];
    __shared__ float qn[HD], kn[HD];

    if (t < HD) {
        qn[t] = fmaxf(sqrtf(g_nq[b * DIM + h * HD + t]), 1e-12f);
        kn[t] = fmaxf(sqrtf(g_nk[b * DIM + h * HD + t]), 1e-12f);
    }
    __syncthreads();
    if (t < HD) {
        int c = t;
        float T = temp[h];
        float inq = T / qn[c];
        const float* Gp = &g_G[((size_t)(b * HEADS + h) * HD + c) * HD];
        float rowv[HD];
        float m = -1e30f;
        #pragma unroll
        for (int d = 0; d < HD; d++) {
            float v = Gp[d] * inq / kn[d];
            rowv[d] = v;
            m = fmaxf(m, v);
        }
        float ssum = 0.f;
        #pragma unroll
        for (int d = 0; d < HD; d++) { rowv[d] = expf(rowv[d] - m); ssum += rowv[d]; }
        float inv = 1.f / ssum;
        #pragma unroll
        for (int d = 0; d < HD; d++) As[c][d] = rowv[d] * inv;
    }
    __syncthreads();

    int o = t;  // 256 threads = 256 output channels
    float wp[HD];
    #pragma unroll
    for (int c = 0; c < HD; c++) wp[c] = w_proj[o * DIM + h * HD + c];
    #pragma unroll 4
    for (int d = 0; d < HD; d++) {
        float s = 0.f;
        #pragma unroll
        for (int c = 0; c < HD; c++) s += wp[c] * As[c][d];
        g_Wc[((size_t)b * DIM + o) * DIM + h * HD + d] = s;
    }
}

// ---------------------------------------------------------------------------
// Launch
// ---------------------------------------------------------------------------
extern "C" void kernel_launch(void* const* d_in, const int* in_sizes, int n_in,
                              void* d_out, int out_size) {
    const float* x      = (const float*)d_in[0];
    const float* k_v    = (const float*)d_in[1];
    const float* temper = (const float*)d_in[2];
    const float* w_kR   = (const float*)d_in[3];
    const float* w_kI   = (const float*)d_in[4];
    const float* w_qR   = (const float*)d_in[5];
    const float* w_qdw  = (const float*)d_in[6];
    const float* w_kvI  = (const float*)d_in[7];
    const float* w_kvdw = (const float*)d_in[8];
    const float* w_proj = (const float*)d_in[9];
    float* out = (float*)d_out;

    zero_kernel<<<136, 256>>>();
    modk_kernel<<<BATCH, 256>>>(k_v, w_kR, w_kI, w_qR, w_kvI);
    gemm_q_kernel <<<dim3(HW / 64, DIM / 64,     BATCH), 256>>>(x);
    gemm_kv_kernel<<<dim3(HW / 64, 2 * DIM / 64, BATCH), 256>>>(x);
    dwq_kernel <<<dim3(8, DIM,     BATCH), 256>>>(w_qdw);
    dwkv_kernel<<<dim3(8, 2 * DIM, BATCH), 256>>>(w_kvdw);
    gram_kernel<<<dim3(32, HEADS, BATCH), 256>>>();
    attn_wc_kernel<<<dim3(HEADS, BATCH), 256>>>(temper, w_proj);
    gemm_o_kernel<<<dim3(HW / 64, DIM / 64, BATCH), 256>>>(out);
}

// round 3
// speedup vs baseline: 1.6113x; 1.6113x over previous
#include <cuda_runtime.h>
#include <cuda_bf16.h>
#include <math.h>
#include <stdint.h>

// Problem constants
#define BATCH 4
#define DIM   256
#define C3    192
#define C1    64
#define HEADS 8
#define HD    32
#define HW    16384   // 128*128
#define IMG   128

// ---------------------------------------------------------------------------
// Device scratch
// ---------------------------------------------------------------------------
__device__ float g_wq [BATCH * DIM * C3];
__device__ float g_wkv[BATCH * 2*DIM * C1];
__device__ float g_tq [BATCH * DIM * HW];
__device__ float g_tkv[BATCH * 2*DIM * HW];
__device__ float g_q  [BATCH * DIM * HW];
__device__ float g_kv [BATCH * 2*DIM * HW];
__device__ float g_nq [BATCH * DIM];
__device__ float g_nk [BATCH * DIM];
__device__ float g_G  [BATCH * HEADS * HD * HD];
__device__ float g_Wc [BATCH * DIM * DIM];

// ---------------------------------------------------------------------------
// Helpers
// ---------------------------------------------------------------------------
__device__ __forceinline__ uint32_t smem_u32(const void* p) {
    uint32_t a;
    asm("{ .reg .u64 t; cvta.to.shared.u64 t, %1; cvt.u32.u64 %0, t; }" : "=r"(a) : "l"(p));
    return a;
}
__device__ __forceinline__ uint32_t f2tf(float x) {
    uint32_t r; asm("cvt.rna.tf32.f32 %0, %1;" : "=r"(r) : "f"(x)); return r;
}
#define CPA16(dst, src) asm volatile("cp.async.cg.shared.global [%0], [%1], 16;" :: "r"(dst), "l"(src) : "memory")
#define CPA_COMMIT()    asm volatile("cp.async.commit_group;" ::: "memory")
#define CPA_WAIT(n)     asm volatile("cp.async.wait_group %0;" :: "n"(n) : "memory")

__device__ __forceinline__ void mma_tf32(float* c, const uint32_t* a, const uint32_t* b) {
    asm volatile(
        "mma.sync.aligned.m16n8k8.row.col.f32.tf32.tf32.f32 "
        "{%0,%1,%2,%3}, {%4,%5,%6,%7}, {%8,%9}, {%0,%1,%2,%3};"
        : "+f"(c[0]), "+f"(c[1]), "+f"(c[2]), "+f"(c[3])
        : "r"(a[0]), "r"(a[1]), "r"(a[2]), "r"(a[3]), "r"(b[0]), "r"(b[1]));
}

// SMEM layout constants (bytes)
#define A_PITCH  36        // floats per A row (32 + pad 4)
#define B_PITCH  136       // floats per B row (128 + pad 8)
#define A_BYTES  (128 * A_PITCH * 4)          // 18432
#define B_BYTES  (32 * B_PITCH * 4)           // 17408
#define STAGE_BYTES (A_BYTES + B_BYTES)       // 35840
#define SMEM_TOTAL (2 * STAGE_BYTES)          // 71680
#define C_PITCH  68        // floats per Cs row (64 + pad 4)

// ---------------------------------------------------------------------------
// Zero accumulated buffers
// ---------------------------------------------------------------------------
__global__ void zero_kernel() {
    int i = blockIdx.x * blockDim.x + threadIdx.x;
    if (i < BATCH * DIM) { g_nq[i] = 0.f; g_nk[i] = 0.f; }
    if (i < BATCH * HEADS * HD * HD) g_G[i] = 0.f;
}

// ---------------------------------------------------------------------------
// FiLM folded into per-batch weights
// ---------------------------------------------------------------------------
__global__ void modk_kernel(const float* __restrict__ k_v,
                            const float* __restrict__ w_kR,
                            const float* __restrict__ w_kI,
                            const float* __restrict__ w_qR,
                            const float* __restrict__ w_kvI) {
    int b = blockIdx.x;
    int t = threadIdx.x;
    __shared__ float sc[DIM];
    if (t < C3) {
        float s = 0.f;
        const float* kb = k_v + b * 256;
        for (int i = 0; i < 192; i++) s += kb[i] * w_kR[t * 192 + i];
        sc[t] = 1.f + s;
    } else {
        int o = t - C3;
        float s = 0.f;
        const float* kb = k_v + b * 256 + 192;
        for (int i = 0; i < 64; i++) s += kb[i] * w_kI[o * 64 + i];
        sc[t] = 1.f + s;
    }
    __syncthreads();
    for (int idx = t; idx < DIM * C3; idx += blockDim.x)
        g_wq[b * DIM * C3 + idx] = w_qR[idx] * sc[idx % C3];
    for (int idx = t; idx < 2 * DIM * C1; idx += blockDim.x)
        g_wkv[b * 2 * DIM * C1 + idx] = w_kvI[idx] * sc[C3 + (idx & 63)];
}

// ---------------------------------------------------------------------------
// tf32 mma.sync GEMM: C[b][o][n] = sum_k W[b][o][k] * X[b*xbs + xoff + k][n]
// Block: 128(M=o) x 128(N=hw), BK=32, 8 warps (2Mx4N), warp tile 64x32.
// Double-buffered cp.async. Epilogue staged through SMEM for coalesced STG.
// ---------------------------------------------------------------------------
template <int K, int OC>
__device__ __forceinline__ void mma_gemm_body(const float* __restrict__ W,
                                              const float* __restrict__ X,
                                              float* __restrict__ C,
                                              int x_bstride, int x_off) {
    extern __shared__ char smem[];
    const int b  = blockIdx.z;
    const int n0 = blockIdx.x * 128;
    const int o0 = blockIdx.y * 128;
    const float* Wb = W + (size_t)b * OC * K + (size_t)o0 * K;
    const float* Xb = X + (size_t)b * x_bstride + x_off + n0;
    float*       Cb = C + (size_t)b * OC * HW + (size_t)o0 * HW + n0;

    const int t = threadIdx.x;
    const int warp = t >> 5, lane = t & 31;
    const int wm = warp >> 2, wn = warp & 3;  // 2 x 4 warp grid
    const int g = lane >> 2, tg = lane & 3;   // mma group / in-group

    const uint32_t sbase = smem_u32(smem);
    const int am = t >> 3;            // A load row base
    const int a16 = (t & 7) * 16;     // A load 16B offset within row
    const int bn16 = (t & 31) * 16;   // B load 16B offset within row
    const int bk = t >> 5;            // B load row base

    float acc[4][4][4];
    #pragma unroll
    for (int i = 0; i < 4; i++)
        #pragma unroll
        for (int j = 0; j < 4; j++)
            #pragma unroll
            for (int r = 0; r < 4; r++) acc[i][j][r] = 0.f;

    constexpr int NCHUNK = K / 32;

    // prefetch chunk 0
    {
        uint32_t ab = sbase;
        uint32_t bb = sbase + A_BYTES;
        #pragma unroll
        for (int i = 0; i < 4; i++) {
            int m = am + 32 * i;
            CPA16(ab + m * (A_PITCH * 4) + a16, Wb + (size_t)m * K + (a16 >> 2));
        }
        #pragma unroll
        for (int i = 0; i < 4; i++) {
            int kk = bk + 8 * i;
            CPA16(bb + kk * (B_PITCH * 4) + bn16, Xb + (size_t)kk * HW + (bn16 >> 2));
        }
        CPA_COMMIT();
    }

    #pragma unroll 1
    for (int c = 0; c < NCHUNK; c++) {
        if (c + 1 < NCHUNK) {
            int s = (c + 1) & 1;
            int k0 = (c + 1) * 32;
            uint32_t ab = sbase + s * STAGE_BYTES;
            uint32_t bb = ab + A_BYTES;
            #pragma unroll
            for (int i = 0; i < 4; i++) {
                int m = am + 32 * i;
                CPA16(ab + m * (A_PITCH * 4) + a16, Wb + (size_t)m * K + k0 + (a16 >> 2));
            }
            #pragma unroll
            for (int i = 0; i < 4; i++) {
                int kk = bk + 8 * i;
                CPA16(bb + kk * (B_PITCH * 4) + bn16, Xb + (size_t)(k0 + kk) * HW + (bn16 >> 2));
            }
            CPA_COMMIT();
            CPA_WAIT(1);
        } else {
            CPA_WAIT(0);
        }
        __syncthreads();

        const float* As = reinterpret_cast<const float*>(smem + (c & 1) * STAGE_BYTES);
        const float* Bs = reinterpret_cast<const float*>(smem + (c & 1) * STAGE_BYTES + A_BYTES);

        #pragma unroll
        for (int ks = 0; ks < 4; ks++) {
            uint32_t afr[4][4];
            #pragma unroll
            for (int mf = 0; mf < 4; mf++) {
                int m = wm * 64 + mf * 16 + g;
                int k = ks * 8 + tg;
                afr[mf][0] = f2tf(As[m * A_PITCH + k]);
                afr[mf][1] = f2tf(As[(m + 8) * A_PITCH + k]);
                afr[mf][2] = f2tf(As[m * A_PITCH + k + 4]);
                afr[mf][3] = f2tf(As[(m + 8) * A_PITCH + k + 4]);
            }
            uint32_t bfr[4][2];
            #pragma unroll
            for (int nf = 0; nf < 4; nf++) {
                int n = wn * 32 + nf * 8 + g;
                int k = ks * 8 + tg;
                bfr[nf][0] = f2tf(Bs[k * B_PITCH + n]);
                bfr[nf][1] = f2tf(Bs[(k + 4) * B_PITCH + n]);
            }
            #pragma unroll
            for (int mf = 0; mf < 4; mf++)
                #pragma unroll
                for (int nf = 0; nf < 4; nf++)
                    mma_tf32(acc[mf][nf], afr[mf], bfr[nf]);
        }
        __syncthreads();
    }

    // Epilogue: stage through SMEM (reuses buffers), coalesced 16B stores.
    float* Cs = reinterpret_cast<float*>(smem);
    #pragma unroll
    for (int half = 0; half < 2; half++) {
        if ((wn >> 1) == half) {
            int cb = wn * 32 - half * 64;
            #pragma unroll
            for (int mf = 0; mf < 4; mf++) {
                #pragma unroll
                for (int nf = 0; nf < 4; nf++) {
                    int row = wm * 64 + mf * 16 + g;
                    int col = cb + nf * 8 + tg * 2;
                    *reinterpret_cast<float2*>(&Cs[row * C_PITCH + col]) =
                        make_float2(acc[mf][nf][0], acc[mf][nf][1]);
                    *reinterpret_cast<float2*>(&Cs[(row + 8) * C_PITCH + col]) =
                        make_float2(acc[mf][nf][2], acc[mf][nf][3]);
                }
            }
        }
        __syncthreads();
        #pragma unroll
        for (int i = 0; i < 8; i++) {
            int r = (t >> 4) + 16 * i;
            int col = (t & 15) * 4;
            float4 v = *reinterpret_cast<const float4*>(&Cs[r * C_PITCH + col]);
            *reinterpret_cast<float4*>(&Cb[(size_t)r * HW + half * 64 + col]) = v;
        }
        __syncthreads();
    }
}

__global__ void __launch_bounds__(256) mma_q_kernel(const float* __restrict__ x) {
    mma_gemm_body<C3, DIM>(g_wq, x, g_tq, DIM * HW, 0);
}
__global__ void __launch_bounds__(256) mma_kv_kernel(const float* __restrict__ x) {
    mma_gemm_body<C1, 2 * DIM>(g_wkv, x, g_tkv, DIM * HW, C3 * HW);
}
__global__ void __launch_bounds__(256) mma_o_kernel(float* __restrict__ out) {
    mma_gemm_body<DIM, DIM>(g_Wc, g_kv, out, 2 * DIM * HW, DIM * HW);
}

// ---------------------------------------------------------------------------
// Depthwise 3x3 conv + row sum-of-squares
// ---------------------------------------------------------------------------
__device__ __forceinline__ void dwconv_body(const float* __restrict__ in,
                                            const float* __restrict__ w9,
                                            float* __restrict__ out,
                                            int C, float* norms, int normC) {
    int b = blockIdx.z, c = blockIdx.y, chunk = blockIdx.x;
    const float* ip = in + (size_t)(b * C + c) * HW;
    float*       op = out + (size_t)(b * C + c) * HW;
    float wv[9];
    #pragma unroll
    for (int i = 0; i < 9; i++) wv[i] = w9[c * 9 + i];
    float ss = 0.f;
    #pragma unroll
    for (int it = 0; it < 8; it++) {
        int p = chunk * 2048 + it * 256 + threadIdx.x;
        int y = p >> 7, x = p & 127;
        float s = 0.f;
        #pragma unroll
        for (int dy = -1; dy <= 1; dy++) {
            int yy = y + dy;
            if ((unsigned)yy < (unsigned)IMG) {
                const float* rp = ip + yy * IMG;
                #pragma unroll
                for (int dx = -1; dx <= 1; dx++) {
                    int xx = x + dx;
                    if ((unsigned)xx < (unsigned)IMG)
                        s += wv[(dy + 1) * 3 + dx + 1] * rp[xx];
                }
            }
        }
        op[p] = s;
        ss += s * s;
    }
    if (c < normC) {
        #pragma unroll
        for (int o = 16; o > 0; o >>= 1) ss += __shfl_down_sync(0xffffffffu, ss, o);
        __shared__ float red[8];
        if ((threadIdx.x & 31) == 0) red[threadIdx.x >> 5] = ss;
        __syncthreads();
        if (threadIdx.x < 8) {
            float v = red[threadIdx.x];
            #pragma unroll
            for (int o = 4; o > 0; o >>= 1) v += __shfl_down_sync(0x000000ffu, v, o, 8);
            if (threadIdx.x == 0) atomicAdd(&norms[b * DIM + c], v);
        }
    }
}

__global__ void __launch_bounds__(256) dwq_kernel(const float* __restrict__ w) {
    dwconv_body(g_tq, w, g_q, DIM, g_nq, DIM);
}
__global__ void __launch_bounds__(256) dwkv_kernel(const float* __restrict__ w) {
    dwconv_body(g_tkv, w, g_kv, 2 * DIM, g_nk, DIM);
}

// ---------------------------------------------------------------------------
// Gram matrices
// ---------------------------------------------------------------------------
__global__ void __launch_bounds__(256) gram_kernel() {
    int chunk = blockIdx.x, h = blockIdx.y, b = blockIdx.z;
    const float* qp = g_q  + (size_t)(b * DIM      + h * HD) * HW;
    const float* kp = g_kv + (size_t)(b * 2 * DIM  + h * HD) * HW;

    __shared__ float qs[32][68];
    __shared__ float ks[32][68];

    int t = threadIdx.x;
    int c  = t >> 3;
    int dq = t & 7;
    int row  = t >> 3;
    int lcol = (t & 7) * 8;

    float acc0 = 0.f, acc1 = 0.f, acc2 = 0.f, acc3 = 0.f;

    for (int s = 0; s < 8; s++) {
        int n0 = chunk * 512 + s * 64;
        float4 a0 = *reinterpret_cast<const float4*>(&qp[(size_t)row * HW + n0 + lcol]);
        float4 a1 = *reinterpret_cast<const float4*>(&qp[(size_t)row * HW + n0 + lcol + 4]);
        float4 b0 = *reinterpret_cast<const float4*>(&kp[(size_t)row * HW + n0 + lcol]);
        float4 b1 = *reinterpret_cast<const float4*>(&kp[(size_t)row * HW + n0 + lcol + 4]);
        __syncthreads();
        *reinterpret_cast<float4*>(&qs[row][lcol])     = a0;
        *reinterpret_cast<float4*>(&qs[row][lcol + 4]) = a1;
        *reinterpret_cast<float4*>(&ks[row][lcol])     = b0;
        *reinterpret_cast<float4*>(&ks[row][lcol + 4]) = b1;
        __syncthreads();
        #pragma unroll 8
        for (int j = 0; j < 64; j++) {
            float qv = qs[c][j];
            acc0 += qv * ks[dq     ][j];
            acc1 += qv * ks[dq +  8][j];
            acc2 += qv * ks[dq + 16][j];
            acc3 += qv * ks[dq + 24][j];
        }
    }
    float* Gp = &g_G[((size_t)(b * HEADS + h) * HD + c) * HD];
    atomicAdd(&Gp[dq],      acc0);
    atomicAdd(&Gp[dq + 8],  acc1);
    atomicAdd(&Gp[dq + 16], acc2);
    atomicAdd(&Gp[dq + 24], acc3);
}

// ---------------------------------------------------------------------------
// Softmax + fold attention into w_proj
// ---------------------------------------------------------------------------
__global__ void __launch_bounds__(256) attn_wc_kernel(const float* __restrict__ temp,
                                                      const float* __restrict__ w_proj) {
    int h = blockIdx.x, b = blockIdx.y;
    int t = threadIdx.x;
    __shared__ float As[HD][HD + 1];
    __shared__ float qn[HD], kn[HD];

    if (t < HD) {
        qn[t] = fmaxf(sqrtf(g_nq[b * DIM + h * HD + t]), 1e-12f);
        kn[t] = fmaxf(sqrtf(g_nk[b * DIM + h * HD + t]), 1e-12f);
    }
    __syncthreads();
    if (t < HD) {
        int c = t;
        float T = temp[h];
        float inq = T / qn[c];
        const float* Gp = &g_G[((size_t)(b * HEADS + h) * HD + c) * HD];
        float rowv[HD];
        float m = -1e30f;
        #pragma unroll
        for (int d = 0; d < HD; d++) {
            float v = Gp[d] * inq / kn[d];
            rowv[d] = v;
            m = fmaxf(m, v);
        }
        float ssum = 0.f;
        #pragma unroll
        for (int d = 0; d < HD; d++) { rowv[d] = expf(rowv[d] - m); ssum += rowv[d]; }
        float inv = 1.f / ssum;
        #pragma unroll
        for (int d = 0; d < HD; d++) As[c][d] = rowv[d] * inv;
    }
    __syncthreads();

    int o = t;
    float wp[HD];
    #pragma unroll
    for (int c = 0; c < HD; c++) wp[c] = w_proj[o * DIM + h * HD + c];
    #pragma unroll 4
    for (int d = 0; d < HD; d++) {
        float s = 0.f;
        #pragma unroll
        for (int c = 0; c < HD; c++) s += wp[c] * As[c][d];
        g_Wc[((size_t)b * DIM + o) * DIM + h * HD + d] = s;
    }
}

// ---------------------------------------------------------------------------
// Launch
// ---------------------------------------------------------------------------
extern "C" void kernel_launch(void* const* d_in, const int* in_sizes, int n_in,
                              void* d_out, int out_size) {
    const float* x      = (const float*)d_in[0];
    const float* k_v    = (const float*)d_in[1];
    const float* temper = (const float*)d_in[2];
    const float* w_kR   = (const float*)d_in[3];
    const float* w_kI   = (const float*)d_in[4];
    const float* w_qR   = (const float*)d_in[5];
    const float* w_qdw  = (const float*)d_in[6];
    const float* w_kvI  = (const float*)d_in[7];
    const float* w_kvdw = (const float*)d_in[8];
    const float* w_proj = (const float*)d_in[9];
    float* out = (float*)d_out;

    cudaFuncSetAttribute(mma_q_kernel,  cudaFuncAttributeMaxDynamicSharedMemorySize, SMEM_TOTAL);
    cudaFuncSetAttribute(mma_kv_kernel, cudaFuncAttributeMaxDynamicSharedMemorySize, SMEM_TOTAL);
    cudaFuncSetAttribute(mma_o_kernel,  cudaFuncAttributeMaxDynamicSharedMemorySize, SMEM_TOTAL);

    zero_kernel<<<136, 256>>>();
    modk_kernel<<<BATCH, 256>>>(k_v, w_kR, w_kI, w_qR, w_kvI);
    mma_q_kernel <<<dim3(HW / 128, DIM / 128,     BATCH), 256, SMEM_TOTAL>>>(x);
    mma_kv_kernel<<<dim3(HW / 128, 2 * DIM / 128, BATCH), 256, SMEM_TOTAL>>>(x);
    dwq_kernel <<<dim3(8, DIM,     BATCH), 256>>>(w_qdw);
    dwkv_kernel<<<dim3(8, 2 * DIM, BATCH), 256>>>(w_kvdw);
    gram_kernel<<<dim3(32, HEADS, BATCH), 256>>>();
    attn_wc_kernel<<<dim3(HEADS, BATCH), 256>>>(temper, w_proj);
    mma_o_kernel<<<dim3(HW / 128, DIM / 128, BATCH), 256, SMEM_TOTAL>>>(out);
}

// round 5
// speedup vs baseline: 1.8702x; 1.1607x over previous
#include <cuda_runtime.h>
#include <cuda_bf16.h>
#include <math.h>
#include <stdint.h>

// Problem constants
#define BATCH 4
#define DIM   256
#define C3    192
#define C1    64
#define HEADS 8
#define HD    32
#define HW    16384   // 128*128
#define IMG   128

// ---------------------------------------------------------------------------
// Device scratch
// ---------------------------------------------------------------------------
__device__ float g_wq [BATCH * DIM * C3];
__device__ float g_wkv[BATCH * 2*DIM * C1];
__device__ float g_tq [BATCH * DIM * HW];        // q pre-dwconv
__device__ float g_tkv[BATCH * 2*DIM * HW];      // kv pre-dwconv
__device__ float g_v  [BATCH * DIM * HW];        // v post-dwconv
__device__ float g_nq [BATCH * DIM];
__device__ float g_nk [BATCH * DIM];
__device__ float g_G  [BATCH * HEADS * HD * HD];
__device__ float g_Wc [BATCH * DIM * DIM];

// ---------------------------------------------------------------------------
// Helpers
// ---------------------------------------------------------------------------
__device__ __forceinline__ uint32_t smem_u32(const void* p) {
    uint32_t a;
    asm("{ .reg .u64 t; cvta.to.shared.u64 t, %1; cvt.u32.u64 %0, t; }" : "=r"(a) : "l"(p));
    return a;
}
__device__ __forceinline__ uint32_t f2tf(float x) {
    uint32_t r; asm("cvt.rna.tf32.f32 %0, %1;" : "=r"(r) : "f"(x)); return r;
}
#define CPA16(dst, src) asm volatile("cp.async.cg.shared.global [%0], [%1], 16;" :: "r"(dst), "l"(src) : "memory")
#define CPA_COMMIT()    asm volatile("cp.async.commit_group;" ::: "memory")
#define CPA_WAIT(n)     asm volatile("cp.async.wait_group %0;" :: "n"(n) : "memory")

__device__ __forceinline__ void mma_tf32(float* c, const uint32_t* a, const uint32_t* b) {
    asm volatile(
        "mma.sync.aligned.m16n8k8.row.col.f32.tf32.tf32.f32 "
        "{%0,%1,%2,%3}, {%4,%5,%6,%7}, {%8,%9}, {%0,%1,%2,%3};"
        : "+f"(c[0]), "+f"(c[1]), "+f"(c[2]), "+f"(c[3])
        : "r"(a[0]), "r"(a[1]), "r"(a[2]), "r"(a[3]), "r"(b[0]), "r"(b[1]));
}

// GEMM SMEM layout constants (bytes)
#define A_PITCH  36
#define B_PITCH  136
#define A_BYTES  (128 * A_PITCH * 4)
#define B_BYTES  (32 * B_PITCH * 4)
#define STAGE_BYTES (A_BYTES + B_BYTES)
#define SMEM_TOTAL (2 * STAGE_BYTES)
#define C_PITCH  68

// ---------------------------------------------------------------------------
// Zero accumulated buffers
// ---------------------------------------------------------------------------
__global__ void zero_kernel() {
    int i = blockIdx.x * blockDim.x + threadIdx.x;
    if (i < BATCH * DIM) { g_nq[i] = 0.f; g_nk[i] = 0.f; }
    if (i < BATCH * HEADS * HD * HD) g_G[i] = 0.f;
}

// ---------------------------------------------------------------------------
// FiLM folded into per-batch weights
// ---------------------------------------------------------------------------
__global__ void modk_kernel(const float* __restrict__ k_v,
                            const float* __restrict__ w_kR,
                            const float* __restrict__ w_kI,
                            const float* __restrict__ w_qR,
                            const float* __restrict__ w_kvI) {
    int b = blockIdx.x;
    int t = threadIdx.x;
    __shared__ float sc[DIM];
    if (t < C3) {
        float s = 0.f;
        const float* kb = k_v + b * 256;
        for (int i = 0; i < 192; i++) s += kb[i] * w_kR[t * 192 + i];
        sc[t] = 1.f + s;
    } else {
        int o = t - C3;
        float s = 0.f;
        const float* kb = k_v + b * 256 + 192;
        for (int i = 0; i < 64; i++) s += kb[i] * w_kI[o * 64 + i];
        sc[t] = 1.f + s;
    }
    __syncthreads();
    for (int idx = t; idx < DIM * C3; idx += blockDim.x)
        g_wq[b * DIM * C3 + idx] = w_qR[idx] * sc[idx % C3];
    for (int idx = t; idx < 2 * DIM * C1; idx += blockDim.x)
        g_wkv[b * 2 * DIM * C1 + idx] = w_kvI[idx] * sc[C3 + (idx & 63)];
}

// ---------------------------------------------------------------------------
// tf32 mma.sync GEMM (unchanged from R3)
// ---------------------------------------------------------------------------
template <int K, int OC>
__device__ __forceinline__ void mma_gemm_body(const float* __restrict__ W,
                                              const float* __restrict__ X,
                                              float* __restrict__ C,
                                              int x_bstride, int x_off) {
    extern __shared__ char smem[];
    const int b  = blockIdx.z;
    const int n0 = blockIdx.x * 128;
    const int o0 = blockIdx.y * 128;
    const float* Wb = W + (size_t)b * OC * K + (size_t)o0 * K;
    const float* Xb = X + (size_t)b * x_bstride + x_off + n0;
    float*       Cb = C + (size_t)b * OC * HW + (size_t)o0 * HW + n0;

    const int t = threadIdx.x;
    const int warp = t >> 5, lane = t & 31;
    const int wm = warp >> 2, wn = warp & 3;
    const int g = lane >> 2, tg = lane & 3;

    const uint32_t sbase = smem_u32(smem);
    const int am = t >> 3;
    const int a16 = (t & 7) * 16;
    const int bn16 = (t & 31) * 16;
    const int bk = t >> 5;

    float acc[4][4][4];
    #pragma unroll
    for (int i = 0; i < 4; i++)
        #pragma unroll
        for (int j = 0; j < 4; j++)
            #pragma unroll
            for (int r = 0; r < 4; r++) acc[i][j][r] = 0.f;

    constexpr int NCHUNK = K / 32;

    {
        uint32_t ab = sbase;
        uint32_t bb = sbase + A_BYTES;
        #pragma unroll
        for (int i = 0; i < 4; i++) {
            int m = am + 32 * i;
            CPA16(ab + m * (A_PITCH * 4) + a16, Wb + (size_t)m * K + (a16 >> 2));
        }
        #pragma unroll
        for (int i = 0; i < 4; i++) {
            int kk = bk + 8 * i;
            CPA16(bb + kk * (B_PITCH * 4) + bn16, Xb + (size_t)kk * HW + (bn16 >> 2));
        }
        CPA_COMMIT();
    }

    #pragma unroll 1
    for (int c = 0; c < NCHUNK; c++) {
        if (c + 1 < NCHUNK) {
            int s = (c + 1) & 1;
            int k0 = (c + 1) * 32;
            uint32_t ab = sbase + s * STAGE_BYTES;
            uint32_t bb = ab + A_BYTES;
            #pragma unroll
            for (int i = 0; i < 4; i++) {
                int m = am + 32 * i;
                CPA16(ab + m * (A_PITCH * 4) + a16, Wb + (size_t)m * K + k0 + (a16 >> 2));
            }
            #pragma unroll
            for (int i = 0; i < 4; i++) {
                int kk = bk + 8 * i;
                CPA16(bb + kk * (B_PITCH * 4) + bn16, Xb + (size_t)(k0 + kk) * HW + (bn16 >> 2));
            }
            CPA_COMMIT();
            CPA_WAIT(1);
        } else {
            CPA_WAIT(0);
        }
        __syncthreads();

        const float* As = reinterpret_cast<const float*>(smem + (c & 1) * STAGE_BYTES);
        const float* Bs = reinterpret_cast<const float*>(smem + (c & 1) * STAGE_BYTES + A_BYTES);

        #pragma unroll
        for (int ks = 0; ks < 4; ks++) {
            uint32_t afr[4][4];
            #pragma unroll
            for (int mf = 0; mf < 4; mf++) {
                int m = wm * 64 + mf * 16 + g;
                int k = ks * 8 + tg;
                afr[mf][0] = f2tf(As[m * A_PITCH + k]);
                afr[mf][1] = f2tf(As[(m + 8) * A_PITCH + k]);
                afr[mf][2] = f2tf(As[m * A_PITCH + k + 4]);
                afr[mf][3] = f2tf(As[(m + 8) * A_PITCH + k + 4]);
            }
            uint32_t bfr[4][2];
            #pragma unroll
            for (int nf = 0; nf < 4; nf++) {
                int n = wn * 32 + nf * 8 + g;
                int k = ks * 8 + tg;
                bfr[nf][0] = f2tf(Bs[k * B_PITCH + n]);
                bfr[nf][1] = f2tf(Bs[(k + 4) * B_PITCH + n]);
            }
            #pragma unroll
            for (int mf = 0; mf < 4; mf++)
                #pragma unroll
                for (int nf = 0; nf < 4; nf++)
                    mma_tf32(acc[mf][nf], afr[mf], bfr[nf]);
        }
        __syncthreads();
    }

    float* Cs = reinterpret_cast<float*>(smem);
    #pragma unroll
    for (int half = 0; half < 2; half++) {
        if ((wn >> 1) == half) {
            int cb = wn * 32 - half * 64;
            #pragma unroll
            for (int mf = 0; mf < 4; mf++) {
                #pragma unroll
                for (int nf = 0; nf < 4; nf++) {
                    int row = wm * 64 + mf * 16 + g;
                    int col = cb + nf * 8 + tg * 2;
                    *reinterpret_cast<float2*>(&Cs[row * C_PITCH + col]) =
                        make_float2(acc[mf][nf][0], acc[mf][nf][1]);
                    *reinterpret_cast<float2*>(&Cs[(row + 8) * C_PITCH + col]) =
                        make_float2(acc[mf][nf][2], acc[mf][nf][3]);
                }
            }
        }
        __syncthreads();
        #pragma unroll
        for (int i = 0; i < 8; i++) {
            int r = (t >> 4) + 16 * i;
            int col = (t & 15) * 4;
            float4 v = *reinterpret_cast<const float4*>(&Cs[r * C_PITCH + col]);
            *reinterpret_cast<float4*>(&Cb[(size_t)r * HW + half * 64 + col]) = v;
        }
        __syncthreads();
    }
}

__global__ void __launch_bounds__(256) mma_q_kernel(const float* __restrict__ x) {
    mma_gemm_body<C3, DIM>(g_wq, x, g_tq, DIM * HW, 0);
}
__global__ void __launch_bounds__(256) mma_kv_kernel(const float* __restrict__ x) {
    mma_gemm_body<C1, 2 * DIM>(g_wkv, x, g_tkv, DIM * HW, C3 * HW);
}
__global__ void __launch_bounds__(256) mma_o_kernel(float* __restrict__ out) {
    mma_gemm_body<DIM, DIM>(g_Wc, g_v, out, DIM * HW, 0);
}

// ---------------------------------------------------------------------------
// Fused: dwconv(q) + dwconv(k) + L2 sum-of-squares + 32x32 Gram per head.
// q,k post-conv never touch DRAM. Grid: (16 slabs of 8 rows, HEADS, BATCH).
// SMEM float layout: QC[32][260], KC[32][260], SG[1024], SN[64], WS[576].
// ---------------------------------------------------------------------------
#define FPITCH  260
#define QC_OFF  0
#define KC_OFF  (32 * FPITCH)            // 8320
#define SG_OFF  (2 * 32 * FPITCH)        // 16640
#define SN_OFF  (SG_OFF + 1024)          // 17664
#define WS_OFF  (SN_OFF + 64)            // 17728
#define FUSED_SMEM_BYTES ((WS_OFF + 576) * 4)   // 73216

__global__ void __launch_bounds__(256) fused_qk_gram_kernel(
        const float* __restrict__ w_qdw, const float* __restrict__ w_kvdw) {
    extern __shared__ float sf[];
    const int h = blockIdx.y, b = blockIdx.z;
    const int t = threadIdx.x;
    const int w = t >> 5, lane = t & 31;
    const int yb = blockIdx.x * 8;

    const float* qbase = g_tq  + ((size_t)b * DIM     + h * HD) * HW;
    const float* kbase = g_tkv + ((size_t)b * 2 * DIM + h * HD) * HW;

    for (int i = t; i < 1024 + 64; i += 256) sf[SG_OFF + i] = 0.f;
    for (int i = t; i < 2 * HD * 9; i += 256) {
        int tens = i / 288, r = i % 288;
        sf[WS_OFF + i] = (tens ? w_kvdw : w_qdw)[(h * HD) * 9 + r];
    }
    __syncthreads();

    float acc[4][4] = {};
    const int seg = t >> 6, tt = t & 63, i4 = tt >> 3, j4 = tt & 7;

    #pragma unroll 1
    for (int ch = 0; ch < 4; ch++) {
        const int y = yb + 2 * ch;
        // ---- conv: 128 tasks (2 tensors x 32 ch x 2 rows), one warp-task each
        #pragma unroll 1
        for (int task = w; task < 128; task += 8) {
            int tens = task >> 6;
            int rem = task & 63;
            int c = rem >> 1, rowid = rem & 1;
            const float* plane = (tens ? kbase : qbase) + (size_t)c * HW;
            int oy = y + rowid;
            float4 r0 = (oy > 0)
                ? *reinterpret_cast<const float4*>(plane + (size_t)(oy - 1) * IMG + lane * 4)
                : make_float4(0.f, 0.f, 0.f, 0.f);
            float4 r1 = *reinterpret_cast<const float4*>(plane + (size_t)oy * IMG + lane * 4);
            float4 r2 = (oy < IMG - 1)
                ? *reinterpret_cast<const float4*>(plane + (size_t)(oy + 1) * IMG + lane * 4)
                : make_float4(0.f, 0.f, 0.f, 0.f);
            float l0 = __shfl_up_sync(0xffffffffu, r0.w, 1);
            float l1 = __shfl_up_sync(0xffffffffu, r1.w, 1);
            float l2 = __shfl_up_sync(0xffffffffu, r2.w, 1);
            float h0 = __shfl_down_sync(0xffffffffu, r0.x, 1);
            float h1 = __shfl_down_sync(0xffffffffu, r1.x, 1);
            float h2 = __shfl_down_sync(0xffffffffu, r2.x, 1);
            if (lane == 0)  { l0 = 0.f; l1 = 0.f; l2 = 0.f; }
            if (lane == 31) { h0 = 0.f; h1 = 0.f; h2 = 0.f; }
            const float* w9 = sf + WS_OFF + tens * 288 + c * 9;
            float wa = w9[0], wb = w9[1], wc = w9[2];
            float wd = w9[3], we = w9[4], wf = w9[5];
            float wg = w9[6], wh = w9[7], wi = w9[8];
            float o0 = wa*l0   + wb*r0.x + wc*r0.y + wd*l1   + we*r1.x + wf*r1.y + wg*l2   + wh*r2.x + wi*r2.y;
            float o1 = wa*r0.x + wb*r0.y + wc*r0.z + wd*r1.x + we*r1.y + wf*r1.z + wg*r2.x + wh*r2.y + wi*r2.z;
            float o2 = wa*r0.y + wb*r0.z + wc*r0.w + wd*r1.y + we*r1.z + wf*r1.w + wg*r2.y + wh*r2.z + wi*r2.w;
            float o3 = wa*r0.z + wb*r0.w + wc*h0   + wd*r1.z + we*r1.w + wf*h1   + wg*r2.z + wh*r2.w + wi*h2;
            *reinterpret_cast<float4*>(sf + (tens ? KC_OFF : QC_OFF) + c * FPITCH + rowid * IMG + lane * 4) =
                make_float4(o0, o1, o2, o3);
            float ssq = o0*o0 + o1*o1 + o2*o2 + o3*o3;
            #pragma unroll
            for (int off = 16; off > 0; off >>= 1)
                ssq += __shfl_down_sync(0xffffffffu, ssq, off);
            if (lane == 0) atomicAdd(&sf[SN_OFF + tens * HD + c], ssq);
        }
        __syncthreads();
        // ---- gram over this chunk (256 pixels), 4x4 register tile per thread
        const float* QCp = sf + QC_OFF;
        const float* KCp = sf + KC_OFF;
        #pragma unroll 4
        for (int jj = seg * 64; jj < seg * 64 + 64; jj++) {
            float qv[4], kv[4];
            #pragma unroll
            for (int r = 0; r < 4; r++) qv[r] = QCp[(i4 + 8 * r) * FPITCH + jj];
            #pragma unroll
            for (int s = 0; s < 4; s++) kv[s] = KCp[(j4 + 8 * s) * FPITCH + jj];
            #pragma unroll
            for (int r = 0; r < 4; r++)
                #pragma unroll
                for (int s = 0; s < 4; s++) acc[r][s] += qv[r] * kv[s];
        }
        __syncthreads();
    }
    // ---- reductions
    #pragma unroll
    for (int r = 0; r < 4; r++)
        #pragma unroll
        for (int s = 0; s < 4; s++)
            atomicAdd(&sf[SG_OFF + (i4 + 8 * r) * HD + (j4 + 8 * s)], acc[r][s]);
    __syncthreads();
    float* Gp = g_G + (size_t)(b * HEADS + h) * HD * HD;
    for (int e = t; e < HD * HD; e += 256) atomicAdd(&Gp[e], sf[SG_OFF + e]);
    if (t < 64) {
        float* np = (t < HD) ? g_nq : g_nk;
        atomicAdd(&np[b * DIM + h * HD + (t & 31)], sf[SN_OFF + t]);
    }
}

// ---------------------------------------------------------------------------
// Depthwise 3x3 conv for V only
// ---------------------------------------------------------------------------
__global__ void __launch_bounds__(256) dwv_kernel(const float* __restrict__ w9) {
    int b = blockIdx.z, c = blockIdx.y, chunk = blockIdx.x;
    const float* ip = g_tkv + ((size_t)b * 2 * DIM + DIM + c) * HW;
    float*       op = g_v   + ((size_t)b * DIM + c) * HW;
    float wv[9];
    #pragma unroll
    for (int i = 0; i < 9; i++) wv[i] = w9[(DIM + c) * 9 + i];
    #pragma unroll
    for (int it = 0; it < 8; it++) {
        int p = chunk * 2048 + it * 256 + threadIdx.x;
        int y = p >> 7, x = p & 127;
        float s = 0.f;
        #pragma unroll
        for (int dy = -1; dy <= 1; dy++) {
            int yy = y + dy;
            if ((unsigned)yy < (unsigned)IMG) {
                const float* rp = ip + yy * IMG;
                #pragma unroll
                for (int dx = -1; dx <= 1; dx++) {
                    int xx = x + dx;
                    if ((unsigned)xx < (unsigned)IMG)
                        s += wv[(dy + 1) * 3 + dx + 1] * rp[xx];
                }
            }
        }
        op[p] = s;
    }
}

// ---------------------------------------------------------------------------
// Softmax + fold attention into w_proj
// ---------------------------------------------------------------------------
__global__ void __launch_bounds__(256) attn_wc_kernel(const float* __restrict__ temp,
                                                      const float* __restrict__ w_proj) {
    int h = blockIdx.x, b = blockIdx.y;
    int t = threadIdx.x;
    __shared__ float As[HD][HD + 1];
    __shared__ float qn[HD], kn[HD];

    if (t < HD) {
        qn[t] = fmaxf(sqrtf(g_nq[b * DIM + h * HD + t]), 1e-12f);
        kn[t] = fmaxf(sqrtf(g_nk[b * DIM + h * HD + t]), 1e-12f);
    }
    __syncthreads();
    if (t < HD) {
        int c = t;
        float T = temp[h];
        float inq = T / qn[c];
        const float* Gp = &g_G[((size_t)(b * HEADS + h) * HD + c) * HD];
        float rowv[HD];
        float m = -1e30f;
        #pragma unroll
        for (int d = 0; d < HD; d++) {
            float v = Gp[d] * inq / kn[d];
            rowv[d] = v;
            m = fmaxf(m, v);
        }
        float ssum = 0.f;
        #pragma unroll
        for (int d = 0; d < HD; d++) { rowv[d] = expf(rowv[d] - m); ssum += rowv[d]; }
        float inv = 1.f / ssum;
        #pragma unroll
        for (int d = 0; d < HD; d++) As[c][d] = rowv[d] * inv;
    }
    __syncthreads();

    int o = t;
    float wp[HD];
    #pragma unroll
    for (int c = 0; c < HD; c++) wp[c] = w_proj[o * DIM + h * HD + c];
    #pragma unroll 4
    for (int d = 0; d < HD; d++) {
        float s = 0.f;
        #pragma unroll
        for (int c = 0; c < HD; c++) s += wp[c] * As[c][d];
        g_Wc[((size_t)b * DIM + o) * DIM + h * HD + d] = s;
    }
}

// ---------------------------------------------------------------------------
// Launch
// ---------------------------------------------------------------------------
extern "C" void kernel_launch(void* const* d_in, const int* in_sizes, int n_in,
                              void* d_out, int out_size) {
    const float* x      = (const float*)d_in[0];
    const float* k_v    = (const float*)d_in[1];
    const float* temper = (const float*)d_in[2];
    const float* w_kR   = (const float*)d_in[3];
    const float* w_kI   = (const float*)d_in[4];
    const float* w_qR   = (const float*)d_in[5];
    const float* w_qdw  = (const float*)d_in[6];
    const float* w_kvI  = (const float*)d_in[7];
    const float* w_kvdw = (const float*)d_in[8];
    const float* w_proj = (const float*)d_in[9];
    float* out = (float*)d_out;

    cudaFuncSetAttribute(mma_q_kernel,  cudaFuncAttributeMaxDynamicSharedMemorySize, SMEM_TOTAL);
    cudaFuncSetAttribute(mma_kv_kernel, cudaFuncAttributeMaxDynamicSharedMemorySize, SMEM_TOTAL);
    cudaFuncSetAttribute(mma_o_kernel,  cudaFuncAttributeMaxDynamicSharedMemorySize, SMEM_TOTAL);
    cudaFuncSetAttribute(fused_qk_gram_kernel, cudaFuncAttributeMaxDynamicSharedMemorySize, FUSED_SMEM_BYTES);

    zero_kernel<<<136, 256>>>();
    modk_kernel<<<BATCH, 256>>>(k_v, w_kR, w_kI, w_qR, w_kvI);
    mma_q_kernel <<<dim3(HW / 128, DIM / 128,     BATCH), 256, SMEM_TOTAL>>>(x);
    mma_kv_kernel<<<dim3(HW / 128, 2 * DIM / 128, BATCH), 256, SMEM_TOTAL>>>(x);
    fused_qk_gram_kernel<<<dim3(16, HEADS, BATCH), 256, FUSED_SMEM_BYTES>>>(w_qdw, w_kvdw);
    dwv_kernel<<<dim3(8, DIM, BATCH), 256>>>(w_kvdw);
    attn_wc_kernel<<<dim3(HEADS, BATCH), 256>>>(temper, w_proj);
    mma_o_kernel<<<dim3(HW / 128, DIM / 128, BATCH), 256, SMEM_TOTAL>>>(out);
}

// round 7
// speedup vs baseline: 1.9020x; 1.0170x over previous
#include <cuda_runtime.h>
#include <cuda_bf16.h>
#include <math.h>
#include <stdint.h>

// Problem constants
#define BATCH 4
#define DIM   256
#define C3    192
#define C1    64
#define HEADS 8
#define HD    32
#define HW    16384   // 128*128
#define IMG   128

// ---------------------------------------------------------------------------
// Device scratch
// ---------------------------------------------------------------------------
__device__ float g_wq [BATCH * DIM * C3];        // tf32 bits
__device__ float g_wkv[BATCH * 2*DIM * C1];      // tf32 bits
__device__ float g_tq [BATCH * DIM * HW];        // q pre-dwconv (fp32)
__device__ float g_tkv[BATCH * 2*DIM * HW];      // kv pre-dwconv (fp32)
__device__ float g_v  [BATCH * DIM * HW];        // v post-dwconv (tf32 bits)
__device__ float g_nq [BATCH * DIM];
__device__ float g_nk [BATCH * DIM];
__device__ float g_G  [BATCH * HEADS * HD * HD];
__device__ float g_Wc [BATCH * DIM * DIM];       // tf32 bits

// ---------------------------------------------------------------------------
// Helpers
// ---------------------------------------------------------------------------
__device__ __forceinline__ uint32_t smem_u32(const void* p) {
    uint32_t a;
    asm("{ .reg .u64 t; cvta.to.shared.u64 t, %1; cvt.u32.u64 %0, t; }" : "=r"(a) : "l"(p));
    return a;
}
__device__ __forceinline__ uint32_t f2tf(float x) {
    uint32_t r; asm("cvt.rna.tf32.f32 %0, %1;" : "=r"(r) : "f"(x)); return r;
}
__device__ __forceinline__ float f2tff(float x) {
    return __uint_as_float(f2tf(x));
}
#define CPA16(dst, src) asm volatile("cp.async.cg.shared.global [%0], [%1], 16;" :: "r"(dst), "l"(src) : "memory")
#define CPA_COMMIT()    asm volatile("cp.async.commit_group;" ::: "memory")
#define CPA_WAIT(n)     asm volatile("cp.async.wait_group %0;" :: "n"(n) : "memory")

__device__ __forceinline__ void mma_tf32(float* c, const uint32_t* a, const uint32_t* b) {
    asm volatile(
        "mma.sync.aligned.m16n8k8.row.col.f32.tf32.tf32.f32 "
        "{%0,%1,%2,%3}, {%4,%5,%6,%7}, {%8,%9}, {%0,%1,%2,%3};"
        : "+f"(c[0]), "+f"(c[1]), "+f"(c[2]), "+f"(c[3])
        : "r"(a[0]), "r"(a[1]), "r"(a[2]), "r"(a[3]), "r"(b[0]), "r"(b[1]));
}

// GEMM SMEM layout constants (bytes)
#define A_PITCH  36
#define B_PITCH  136
#define A_BYTES  (128 * A_PITCH * 4)
#define B_BYTES  (32 * B_PITCH * 4)
#define STAGE_BYTES (A_BYTES + B_BYTES)
#define SMEM_TOTAL (2 * STAGE_BYTES)
#define C_PITCH  68

// ---------------------------------------------------------------------------
// FiLM folded into per-batch weights (pre-converted to tf32 bits) + zeroing
// ---------------------------------------------------------------------------
__global__ void modk_kernel(const float* __restrict__ k_v,
                            const float* __restrict__ w_kR,
                            const float* __restrict__ w_kI,
                            const float* __restrict__ w_qR,
                            const float* __restrict__ w_kvI) {
    int b = blockIdx.x;
    int t = threadIdx.x;
    __shared__ float sc[DIM];
    if (t < C3) {
        float s = 0.f;
        const float* kb = k_v + b * 256;
        for (int i = 0; i < 192; i++) s += kb[i] * w_kR[t * 192 + i];
        sc[t] = 1.f + s;
    } else {
        int o = t - C3;
        float s = 0.f;
        const float* kb = k_v + b * 256 + 192;
        for (int i = 0; i < 64; i++) s += kb[i] * w_kI[o * 64 + i];
        sc[t] = 1.f + s;
    }
    __syncthreads();
    for (int idx = t; idx < DIM * C3; idx += blockDim.x)
        g_wq[b * DIM * C3 + idx] = f2tff(w_qR[idx] * sc[idx % C3]);
    for (int idx = t; idx < 2 * DIM * C1; idx += blockDim.x)
        g_wkv[b * 2 * DIM * C1 + idx] = f2tff(w_kvI[idx] * sc[C3 + (idx & 63)]);
    // zero per-batch accumulators
    for (int i = t; i < DIM; i += blockDim.x) {
        g_nq[b * DIM + i] = 0.f;
        g_nk[b * DIM + i] = 0.f;
    }
    for (int i = t; i < HEADS * HD * HD; i += blockDim.x)
        g_G[b * HEADS * HD * HD + i] = 0.f;
}

// ---------------------------------------------------------------------------
// tf32 mma.sync GEMM. A (weights) always pre-converted tf32 bits via cp.async.
// CONV_B: convert B at SMEM-fill (LDG->cvt->STS, reg-prefetch pipelined).
//         otherwise B is pre-converted too and uses cp.async.
// ---------------------------------------------------------------------------
template <int K, int OC, bool CONV_B>
__device__ __forceinline__ void mma_gemm_body(const float* __restrict__ W,
                                              const float* __restrict__ X,
                                              float* __restrict__ C,
                                              int x_bstride, int x_off) {
    extern __shared__ char smem[];
    const int b  = blockIdx.z;
    const int n0 = blockIdx.x * 128;
    const int o0 = blockIdx.y * 128;
    const float* Wb = W + (size_t)b * OC * K + (size_t)o0 * K;
    const float* Xb = X + (size_t)b * x_bstride + x_off + n0;
    float*       Cb = C + (size_t)b * OC * HW + (size_t)o0 * HW + n0;

    const int t = threadIdx.x;
    const int warp = t >> 5, lane = t & 31;
    const int wm = warp >> 2, wn = warp & 3;
    const int g = lane >> 2, tg = lane & 3;

    const uint32_t sbase = smem_u32(smem);
    const int am = t >> 3;
    const int a16 = (t & 7) * 16;
    const int bn16 = (t & 31) * 16;     // byte offset within B row
    const int bk = t >> 5;              // B row base (0..7)

    float acc[4][4][4];
    #pragma unroll
    for (int i = 0; i < 4; i++)
        #pragma unroll
        for (int j = 0; j < 4; j++)
            #pragma unroll
            for (int r = 0; r < 4; r++) acc[i][j][r] = 0.f;

    constexpr int NCHUNK = K / 32;
    float4 bregs[4];

    // ---- prologue: stage 0
    {
        uint32_t ab = sbase;
        uint32_t bb = sbase + A_BYTES;
        #pragma unroll
        for (int i = 0; i < 4; i++) {
            int m = am + 32 * i;
            CPA16(ab + m * (A_PITCH * 4) + a16, Wb + (size_t)m * K + (a16 >> 2));
        }
        if (CONV_B) {
            #pragma unroll
            for (int i = 0; i < 4; i++)
                bregs[i] = *reinterpret_cast<const float4*>(Xb + (size_t)(bk + 8 * i) * HW + (bn16 >> 2));
            CPA_COMMIT();
            #pragma unroll
            for (int i = 0; i < 4; i++) {
                float4 v = bregs[i];
                v.x = f2tff(v.x); v.y = f2tff(v.y); v.z = f2tff(v.z); v.w = f2tff(v.w);
                *reinterpret_cast<float4*>(smem + A_BYTES + (bk + 8 * i) * (B_PITCH * 4) + bn16) = v;
            }
        } else {
            #pragma unroll
            for (int i = 0; i < 4; i++) {
                int kk = bk + 8 * i;
                CPA16(bb + kk * (B_PITCH * 4) + bn16, Xb + (size_t)kk * HW + (bn16 >> 2));
            }
            CPA_COMMIT();
        }
        CPA_WAIT(0);
        __syncthreads();
    }

    #pragma unroll 1
    for (int c = 0; c < NCHUNK; c++) {
        const bool more = (c + 1 < NCHUNK);
        if (more) {
            int s = (c + 1) & 1;
            int k0 = (c + 1) * 32;
            uint32_t ab = sbase + s * STAGE_BYTES;
            uint32_t bb = ab + A_BYTES;
            if (CONV_B) {
                #pragma unroll
                for (int i = 0; i < 4; i++)
                    bregs[i] = *reinterpret_cast<const float4*>(Xb + (size_t)(k0 + bk + 8 * i) * HW + (bn16 >> 2));
            } else {
                #pragma unroll
                for (int i = 0; i < 4; i++) {
                    int kk = bk + 8 * i;
                    CPA16(bb + kk * (B_PITCH * 4) + bn16, Xb + (size_t)(k0 + kk) * HW + (bn16 >> 2));
                }
            }
            #pragma unroll
            for (int i = 0; i < 4; i++) {
                int m = am + 32 * i;
                CPA16(ab + m * (A_PITCH * 4) + a16, Wb + (size_t)m * K + k0 + (a16 >> 2));
            }
            CPA_COMMIT();
        }

        const float* As = reinterpret_cast<const float*>(smem + (c & 1) * STAGE_BYTES);
        const float* Bs = reinterpret_cast<const float*>(smem + (c & 1) * STAGE_BYTES + A_BYTES);
        const uint32_t* Asu = reinterpret_cast<const uint32_t*>(As);
        const uint32_t* Bsu = reinterpret_cast<const uint32_t*>(Bs);

        #pragma unroll
        for (int ks = 0; ks < 4; ks++) {
            uint32_t afr[4][4];
            #pragma unroll
            for (int mf = 0; mf < 4; mf++) {
                int m = wm * 64 + mf * 16 + g;
                int k = ks * 8 + tg;
                afr[mf][0] = Asu[m * A_PITCH + k];
                afr[mf][1] = Asu[(m + 8) * A_PITCH + k];
                afr[mf][2] = Asu[m * A_PITCH + k + 4];
                afr[mf][3] = Asu[(m + 8) * A_PITCH + k + 4];
            }
            uint32_t bfr[4][2];
            #pragma unroll
            for (int nf = 0; nf < 4; nf++) {
                int n = wn * 32 + nf * 8 + g;
                int k = ks * 8 + tg;
                bfr[nf][0] = Bsu[k * B_PITCH + n];
                bfr[nf][1] = Bsu[(k + 4) * B_PITCH + n];
            }
            #pragma unroll
            for (int mf = 0; mf < 4; mf++)
                #pragma unroll
                for (int nf = 0; nf < 4; nf++)
                    mma_tf32(acc[mf][nf], afr[mf], bfr[nf]);
        }

        if (more) {
            if (CONV_B) {
                int s = (c + 1) & 1;
                #pragma unroll
                for (int i = 0; i < 4; i++) {
                    float4 v = bregs[i];
                    v.x = f2tff(v.x); v.y = f2tff(v.y); v.z = f2tff(v.z); v.w = f2tff(v.w);
                    *reinterpret_cast<float4*>(smem + s * STAGE_BYTES + A_BYTES +
                                               (bk + 8 * i) * (B_PITCH * 4) + bn16) = v;
                }
            }
            CPA_WAIT(0);
        }
        __syncthreads();
    }

    // ---- epilogue: stage through SMEM, coalesced 16B stores
    float* Cs = reinterpret_cast<float*>(smem);
    #pragma unroll
    for (int half = 0; half < 2; half++) {
        if ((wn >> 1) == half) {
            int cb = wn * 32 - half * 64;
            #pragma unroll
            for (int mf = 0; mf < 4; mf++) {
                #pragma unroll
                for (int nf = 0; nf < 4; nf++) {
                    int row = wm * 64 + mf * 16 + g;
                    int col = cb + nf * 8 + tg * 2;
                    *reinterpret_cast<float2*>(&Cs[row * C_PITCH + col]) =
                        make_float2(acc[mf][nf][0], acc[mf][nf][1]);
                    *reinterpret_cast<float2*>(&Cs[(row + 8) * C_PITCH + col]) =
                        make_float2(acc[mf][nf][2], acc[mf][nf][3]);
                }
            }
        }
        __syncthreads();
        #pragma unroll
        for (int i = 0; i < 8; i++) {
            int r = (t >> 4) + 16 * i;
            int col = (t & 15) * 4;
            float4 v = *reinterpret_cast<const float4*>(&Cs[r * C_PITCH + col]);
            *reinterpret_cast<float4*>(&Cb[(size_t)r * HW + half * 64 + col]) = v;
        }
        __syncthreads();
    }
}

__global__ void __launch_bounds__(256) mma_q_kernel(const float* __restrict__ x) {
    mma_gemm_body<C3, DIM, true>(g_wq, x, g_tq, DIM * HW, 0);
}
__global__ void __launch_bounds__(256) mma_kv_kernel(const float* __restrict__ x) {
    mma_gemm_body<C1, 2 * DIM, true>(g_wkv, x, g_tkv, DIM * HW, C3 * HW);
}
__global__ void __launch_bounds__(256) mma_o_kernel(float* __restrict__ out) {
    mma_gemm_body<DIM, DIM, false>(g_Wc, g_v, out, DIM * HW, 0);
}

// ---------------------------------------------------------------------------
// Fused: dwconv(q) + dwconv(k) + L2 sum-of-squares + 32x32 Gram per head.
// ---------------------------------------------------------------------------
#define FPITCH  260
#define QC_OFF  0
#define KC_OFF  (32 * FPITCH)
#define SG_OFF  (2 * 32 * FPITCH)
#define SN_OFF  (SG_OFF + 1024)
#define WS_OFF  (SN_OFF + 64)
#define FUSED_SMEM_BYTES ((WS_OFF + 576) * 4)

__global__ void __launch_bounds__(256) fused_qk_gram_kernel(
        const float* __restrict__ w_qdw, const float* __restrict__ w_kvdw) {
    extern __shared__ float sf[];
    const int h = blockIdx.y, b = blockIdx.z;
    const int t = threadIdx.x;
    const int w = t >> 5, lane = t & 31;
    const int yb = blockIdx.x * 8;

    const float* qbase = g_tq  + ((size_t)b * DIM     + h * HD) * HW;
    const float* kbase = g_tkv + ((size_t)b * 2 * DIM + h * HD) * HW;

    for (int i = t; i < 1024 + 64; i += 256) sf[SG_OFF + i] = 0.f;
    for (int i = t; i < 2 * HD * 9; i += 256) {
        int tens = i / 288, r = i % 288;
        sf[WS_OFF + i] = (tens ? w_kvdw : w_qdw)[(h * HD) * 9 + r];
    }
    __syncthreads();

    float acc[4][4] = {};
    const int seg = t >> 6, tt = t & 63, i4 = tt >> 3, j4 = tt & 7;

    #pragma unroll 1
    for (int ch = 0; ch < 4; ch++) {
        const int y = yb + 2 * ch;
        #pragma unroll 1
        for (int task = w; task < 128; task += 8) {
            int tens = task >> 6;
            int rem = task & 63;
            int c = rem >> 1, rowid = rem & 1;
            const float* plane = (tens ? kbase : qbase) + (size_t)c * HW;
            int oy = y + rowid;
            float4 r0 = (oy > 0)
                ? *reinterpret_cast<const float4*>(plane + (size_t)(oy - 1) * IMG + lane * 4)
                : make_float4(0.f, 0.f, 0.f, 0.f);
            float4 r1 = *reinterpret_cast<const float4*>(plane + (size_t)oy * IMG + lane * 4);
            float4 r2 = (oy < IMG - 1)
                ? *reinterpret_cast<const float4*>(plane + (size_t)(oy + 1) * IMG + lane * 4)
                : make_float4(0.f, 0.f, 0.f, 0.f);
            float l0 = __shfl_up_sync(0xffffffffu, r0.w, 1);
            float l1 = __shfl_up_sync(0xffffffffu, r1.w, 1);
            float l2 = __shfl_up_sync(0xffffffffu, r2.w, 1);
            float h0 = __shfl_down_sync(0xffffffffu, r0.x, 1);
            float h1 = __shfl_down_sync(0xffffffffu, r1.x, 1);
            float h2 = __shfl_down_sync(0xffffffffu, r2.x, 1);
            if (lane == 0)  { l0 = 0.f; l1 = 0.f; l2 = 0.f; }
            if (lane == 31) { h0 = 0.f; h1 = 0.f; h2 = 0.f; }
            const float* w9 = sf + WS_OFF + tens * 288 + c * 9;
            float wa = w9[0], wb = w9[1], wc = w9[2];
            float wd = w9[3], we = w9[4], wf = w9[5];
            float wg = w9[6], wh = w9[7], wi = w9[8];
            float o0 = wa*l0   + wb*r0.x + wc*r0.y + wd*l1   + we*r1.x + wf*r1.y + wg*l2   + wh*r2.x + wi*r2.y;
            float o1 = wa*r0.x + wb*r0.y + wc*r0.z + wd*r1.x + we*r1.y + wf*r1.z + wg*r2.x + wh*r2.y + wi*r2.z;
            float o2 = wa*r0.y + wb*r0.z + wc*r0.w + wd*r1.y + we*r1.z + wf*r1.w + wg*r2.y + wh*r2.z + wi*r2.w;
            float o3 = wa*r0.z + wb*r0.w + wc*h0   + wd*r1.z + we*r1.w + wf*h1   + wg*r2.z + wh*r2.w + wi*h2;
            *reinterpret_cast<float4*>(sf + (tens ? KC_OFF : QC_OFF) + c * FPITCH + rowid * IMG + lane * 4) =
                make_float4(o0, o1, o2, o3);
            float ssq = o0*o0 + o1*o1 + o2*o2 + o3*o3;
            #pragma unroll
            for (int off = 16; off > 0; off >>= 1)
                ssq += __shfl_down_sync(0xffffffffu, ssq, off);
            if (lane == 0) atomicAdd(&sf[SN_OFF + tens * HD + c], ssq);
        }
        __syncthreads();
        // ---- gram over this chunk (256 pixels), vectorized LDS.128
        const float* QCp = sf + QC_OFF;
        const float* KCp = sf + KC_OFF;
        #pragma unroll 2
        for (int jj = seg * 64; jj < seg * 64 + 64; jj += 4) {
            float4 q4[4], k4[4];
            #pragma unroll
            for (int r = 0; r < 4; r++)
                q4[r] = *reinterpret_cast<const float4*>(&QCp[(i4 + 8 * r) * FPITCH + jj]);
            #pragma unroll
            for (int s = 0; s < 4; s++)
                k4[s] = *reinterpret_cast<const float4*>(&KCp[(j4 + 8 * s) * FPITCH + jj]);
            #pragma unroll
            for (int r = 0; r < 4; r++)
                #pragma unroll
                for (int s = 0; s < 4; s++)
                    acc[r][s] += q4[r].x * k4[s].x + q4[r].y * k4[s].y
                               + q4[r].z * k4[s].z + q4[r].w * k4[s].w;
        }
        __syncthreads();
    }
    #pragma unroll
    for (int r = 0; r < 4; r++)
        #pragma unroll
        for (int s = 0; s < 4; s++)
            atomicAdd(&sf[SG_OFF + (i4 + 8 * r) * HD + (j4 + 8 * s)], acc[r][s]);
    __syncthreads();
    float* Gp = g_G + (size_t)(b * HEADS + h) * HD * HD;
    for (int e = t; e < HD * HD; e += 256) atomicAdd(&Gp[e], sf[SG_OFF + e]);
    if (t < 64) {
        float* np = (t < HD) ? g_nq : g_nk;
        atomicAdd(&np[b * DIM + h * HD + (t & 31)], sf[SN_OFF + t]);
    }
}

// ---------------------------------------------------------------------------
// Depthwise 3x3 conv for V (stores tf32 bits for the o-GEMM)
// ---------------------------------------------------------------------------
__global__ void __launch_bounds__(256) dwv_kernel(const float* __restrict__ w9) {
    int b = blockIdx.z, c = blockIdx.y, chunk = blockIdx.x;
    const float* ip = g_tkv + ((size_t)b * 2 * DIM + DIM + c) * HW;
    float*       op = g_v   + ((size_t)b * DIM + c) * HW;
    float wv[9];
    #pragma unroll
    for (int i = 0; i < 9; i++) wv[i] = w9[(DIM + c) * 9 + i];
    #pragma unroll
    for (int it = 0; it < 8; it++) {
        int p = chunk * 2048 + it * 256 + threadIdx.x;
        int y = p >> 7, x = p & 127;
        float s = 0.f;
        #pragma unroll
        for (int dy = -1; dy <= 1; dy++) {
            int yy = y + dy;
            if ((unsigned)yy < (unsigned)IMG) {
                const float* rp = ip + yy * IMG;
                #pragma unroll
                for (int dx = -1; dx <= 1; dx++) {
                    int xx = x + dx;
                    if ((unsigned)xx < (unsigned)IMG)
                        s += wv[(dy + 1) * 3 + dx + 1] * rp[xx];
                }
            }
        }
        op[p] = f2tff(s);
    }
}

// ---------------------------------------------------------------------------
// Softmax + fold attention into w_proj (stores tf32 bits)
// ---------------------------------------------------------------------------
__global__ void __launch_bounds__(256) attn_wc_kernel(const float* __restrict__ temp,
                                                      const float* __restrict__ w_proj) {
    int h = blockIdx.x, b = blockIdx.y;
    int t = threadIdx.x;
    __shared__ float As[HD][HD + 1];
    __shared__ float qn[HD], kn[HD];

    if (t < HD) {
        qn[t] = fmaxf(sqrtf(g_nq[b * DIM + h * HD + t]), 1e-12f);
        kn[t] = fmaxf(sqrtf(g_nk[b * DIM + h * HD + t]), 1e-12f);
    }
    __syncthreads();
    if (t < HD) {
        int c = t;
        float T = temp[h];
        float inq = T / qn[c];
        const float* Gp = &g_G[((size_t)(b * HEADS + h) * HD + c) * HD];
        float rowv[HD];
        float m = -1e30f;
        #pragma unroll
        for (int d = 0; d < HD; d++) {
            float v = Gp[d] * inq / kn[d];
            rowv[d] = v;
            m = fmaxf(m, v);
        }
        float ssum = 0.f;
        #pragma unroll
        for (int d = 0; d < HD; d++) { rowv[d] = expf(rowv[d] - m); ssum += rowv[d]; }
        float inv = 1.f / ssum;
        #pragma unroll
        for (int d = 0; d < HD; d++) As[c][d] = rowv[d] * inv;
    }
    __syncthreads();

    int o = t;
    float wp[HD];
    #pragma unroll
    for (int c = 0; c < HD; c++) wp[c] = w_proj[o * DIM + h * HD + c];
    #pragma unroll 4
    for (int d = 0; d < HD; d++) {
        float s = 0.f;
        #pragma unroll
        for (int c = 0; c < HD; c++) s += wp[c] * As[c][d];
        g_Wc[((size_t)b * DIM + o) * DIM + h * HD + d] = f2tff(s);
    }
}

// ---------------------------------------------------------------------------
// Launch
// ---------------------------------------------------------------------------
extern "C" void kernel_launch(void* const* d_in, const int* in_sizes, int n_in,
                              void* d_out, int out_size) {
    const float* x      = (const float*)d_in[0];
    const float* k_v    = (const float*)d_in[1];
    const float* temper = (const float*)d_in[2];
    const float* w_kR   = (const float*)d_in[3];
    const float* w_kI   = (const float*)d_in[4];
    const float* w_qR   = (const float*)d_in[5];
    const float* w_qdw  = (const float*)d_in[6];
    const float* w_kvI  = (const float*)d_in[7];
    const float* w_kvdw = (const float*)d_in[8];
    const float* w_proj = (const float*)d_in[9];
    float* out = (float*)d_out;

    cudaFuncSetAttribute(mma_q_kernel,  cudaFuncAttributeMaxDynamicSharedMemorySize, SMEM_TOTAL);
    cudaFuncSetAttribute(mma_kv_kernel, cudaFuncAttributeMaxDynamicSharedMemorySize, SMEM_TOTAL);
    cudaFuncSetAttribute(mma_o_kernel,  cudaFuncAttributeMaxDynamicSharedMemorySize, SMEM_TOTAL);
    cudaFuncSetAttribute(fused_qk_gram_kernel, cudaFuncAttributeMaxDynamicSharedMemorySize, FUSED_SMEM_BYTES);

    modk_kernel<<<BATCH, 256>>>(k_v, w_kR, w_kI, w_qR, w_kvI);
    mma_q_kernel <<<dim3(HW / 128, DIM / 128,     BATCH), 256, SMEM_TOTAL>>>(x);
    mma_kv_kernel<<<dim3(HW / 128, 2 * DIM / 128, BATCH), 256, SMEM_TOTAL>>>(x);
    fused_qk_gram_kernel<<<dim3(16, HEADS, BATCH), 256, FUSED_SMEM_BYTES>>>(w_qdw, w_kvdw);
    dwv_kernel<<<dim3(8, DIM, BATCH), 256>>>(w_kvdw);
    attn_wc_kernel<<<dim3(HEADS, BATCH), 256>>>(temper, w_proj);
    mma_o_kernel<<<dim3(HW / 128, DIM / 128, BATCH), 256, SMEM_TOTAL>>>(out);
}